// round 9
// baseline (speedup 1.0000x reference)
#include <cuda_runtime.h>
#include <stdint.h>

#define SEQ   4096
#define NPOS  32768
#define SLOT  80
#define ROW_BYTES (SLOT * 4)                 // 320
#define NTAB  16
#define POS_BYTES (NTAB * ROW_BYTES)         // 5120 per position
#define P     2                              // positions per block
#define THREADS 64                           // 32 threads per position
#define STAGE_BYTES (P * POS_BYTES)          // 10240
#define NBLOCKS (NPOS / P)                   // 16384
#define N3_BYTES (P * 8 * ROW_BYTES)         // 5120 via TMA

// table sizes: 8 x n=2 then 8 x n=3
__constant__ unsigned int c_sizes[16] = {
    6619u, 6637u, 6653u, 6659u, 6661u, 6673u, 6679u, 6689u,
    65521u, 65537u, 65539u, 65543u, 65551u, 65557u, 65563u, 65579u
};

struct Tables { const float* t[16]; };

__device__ __forceinline__ uint32_t smem_u32(const void* p) {
    uint32_t a;
    asm("{ .reg .u64 tmp; cvta.to.shared.u64 tmp, %1; cvt.u32.u64 %0, tmp; }"
        : "=r"(a) : "l"(p));
    return a;
}

__global__ __launch_bounds__(THREADS) void engram_kernel(
    const int* __restrict__ ids,      // [B, S] int32
    const int* __restrict__ seeds,    // [3, 8] int32
    Tables tp,
    float* __restrict__ out)          // [B, S, 1280] fp32
{
    __shared__ __align__(16) unsigned char stage[STAGE_BYTES];
    __shared__ __align__(8)  unsigned long long mbar;
    __shared__ const float* rowptr[P][8];     // n2 row pointers

    const int tid = threadIdx.x;
    const uint32_t stage_a = smem_u32(stage);
    const uint32_t mbar_a  = smem_u32(&mbar);

    if (tid == 0) {
        asm volatile("mbarrier.init.shared.b64 [%0], 1;" :: "r"(mbar_a) : "memory");
    }
    __syncthreads();
    if (tid == 0) {
        asm volatile("mbarrier.arrive.expect_tx.shared.b64 _, [%0], %1;"
                     :: "r"(mbar_a), "r"((int)N3_BYTES) : "memory");
    }

    const int pl  = tid >> 5;            // position within block (one warp each)
    const int t   = tid & 31;
    const int pos = blockIdx.x * P + pl;
    const int s   = pos & (SEQ - 1);

    // L2 policies
    uint64_t pol_ef, pol_el;
    asm("createpolicy.fractional.L2::evict_first.b64 %0, 1.0;" : "=l"(pol_ef));
    asm("createpolicy.fractional.L2::evict_last.b64 %0, 1.0;"  : "=l"(pol_el));

    // 16 hash threads per position
    if (t < 16) {
        const int tab  = t;
        const int head = tab & 7;

        const unsigned long long id0 = (unsigned int)__ldg(ids + pos);
        const unsigned long long id1 =
            (s >= 1) ? (unsigned long long)(unsigned int)__ldg(ids + pos - 1) : 0ull;

        unsigned long long h;
        if (tab < 8) {
            h = (id1 * (unsigned long long)(unsigned int)__ldg(seeds + head))
              ^ (id0 * (unsigned long long)(unsigned int)__ldg(seeds + 8 + head));
        } else {
            const unsigned long long id2 =
                (s >= 2) ? (unsigned long long)(unsigned int)__ldg(ids + pos - 2) : 0ull;
            h = (id2 * (unsigned long long)(unsigned int)__ldg(seeds + head))
              ^ (id1 * (unsigned long long)(unsigned int)__ldg(seeds + 8 + head))
              ^ (id0 * (unsigned long long)(unsigned int)__ldg(seeds + 16 + head));
        }
        const unsigned int idx = (unsigned int)(h % (unsigned long long)c_sizes[tab]);

        if (tab < 8) {
            // n2: L2-resident — gather via LDG below
            rowptr[pl][tab] = tp.t[tab] + (size_t)idx * SLOT;
        } else {
            // n3: DRAM-latency — TMA bulk copy, pinned in L2
            const char*    src = (const char*)tp.t[tab] + (size_t)idx * ROW_BYTES;
            const uint32_t dst = stage_a + (uint32_t)(pl * POS_BYTES + tab * ROW_BYTES);
            asm volatile(
                "cp.async.bulk.shared::cta.global.mbarrier::complete_tx::bytes.L2::cache_hint "
                "[%0], [%1], %2, [%3], %4;"
                :: "r"(dst), "l"(src), "r"((int)ROW_BYTES), "r"(mbar_a), "l"(pol_el)
                : "memory");
        }
    }
    __syncwarp();

    // cooperative LDG gather of the 8 n2 rows: 160 float4 per position,
    // 5 independent loads per thread (high MLP, all L2 hits)
    const float4* ap[5];
    #pragma unroll
    for (int i = 0; i < 5; i++) {
        const int f   = i * 32 + t;          // 0..159
        const int row = f / 20;
        const int q   = f - row * 20;
        ap[i] = ((const float4*)rowptr[pl][row]) + q;
    }
    float4 v[5];
    #pragma unroll
    for (int i = 0; i < 5; i++) v[i] = __ldg(ap[i]);
    #pragma unroll
    for (int i = 0; i < 5; i++) {
        const int f   = i * 32 + t;
        const int row = f / 20;
        const int q   = f - row * 20;
        *(float4*)(stage + pl * POS_BYTES + row * ROW_BYTES + q * 16) = v[i];
    }
    __syncthreads();

    // single drain: wait n3 TMA arrivals, order STS into async proxy,
    // one contiguous 10KB bulk store for both positions
    if (tid == 0) {
        asm volatile("fence.proxy.async.shared::cta;" ::: "memory");
        asm volatile(
            "{\n\t"
            ".reg .pred P1;\n\t"
            "W_%=:\n\t"
            "mbarrier.try_wait.parity.shared.b64 P1, [%0], 0, 0x989680;\n\t"
            "@P1 bra.uni D_%=;\n\t"
            "bra.uni W_%=;\n\t"
            "D_%=:\n\t"
            "}"
            :: "r"(mbar_a) : "memory");

        char* gdst = (char*)out + (size_t)blockIdx.x * STAGE_BYTES;
        asm volatile(
            "cp.async.bulk.global.shared::cta.bulk_group.L2::cache_hint "
            "[%0], [%1], %2, %3;"
            :: "l"(gdst), "r"(stage_a), "r"((int)STAGE_BYTES), "l"(pol_ef)
            : "memory");
        asm volatile("cp.async.bulk.commit_group;" ::: "memory");
        asm volatile("cp.async.bulk.wait_group.read 0;" ::: "memory");
    }
}

extern "C" void kernel_launch(void* const* d_in, const int* in_sizes, int n_in,
                              void* d_out, int out_size)
{
    const int* ids   = (const int*)d_in[0];
    const int* seeds = (const int*)d_in[1];

    Tables tp;
    #pragma unroll
    for (int i = 0; i < 16; i++) tp.t[i] = (const float*)d_in[2 + i];

    engram_kernel<<<NBLOCKS, THREADS>>>(ids, seeds, tp, (float*)d_out);
}

// round 11
// speedup vs baseline: 1.0219x; 1.0219x over previous
#include <cuda_runtime.h>
#include <cuda.h>
#include <stdint.h>

#define SEQ   4096
#define NPOS  32768
#define SLOT  80
#define ROW_BYTES (SLOT * 4)                 // 320
#define NTAB  16
#define POS_BYTES (NTAB * ROW_BYTES)         // 5120
#define P4    4                              // positions per block
#define TAB_STRIDE (P4 * ROW_BYTES)          // 1280 (gather4 result per table)
#define STAGE_BYTES (P4 * POS_BYTES)         // 20480
#define G4_BLOCKS (NPOS / P4)                // 8192
#define G4_THREADS 128

__constant__ unsigned int c_sizes[16] = {
    6619u, 6637u, 6653u, 6659u, 6661u, 6673u, 6679u, 6689u,
    65521u, 65537u, 65539u, 65543u, 65551u, 65557u, 65563u, 65579u
};

static const unsigned int h_sizes[16] = {
    6619u, 6637u, 6653u, 6659u, 6661u, 6673u, 6679u, 6689u,
    65521u, 65537u, 65539u, 65543u, 65551u, 65557u, 65563u, 65579u
};

struct Tables { const float* t[16]; };
struct TMaps  { CUtensorMap m[16]; };

__device__ __forceinline__ uint32_t smem_u32(const void* p) {
    uint32_t a;
    asm("{ .reg .u64 tmp; cvta.to.shared.u64 tmp, %1; cvt.u32.u64 %0, tmp; }"
        : "=r"(a) : "l"(p));
    return a;
}

// ==================== gather4 + transpose + single bulk store ====================
__global__ __launch_bounds__(G4_THREADS) void engram_g4_kernel(
    const int* __restrict__ ids,
    const int* __restrict__ seeds,
    const __grid_constant__ TMaps maps,
    float* __restrict__ out)
{
    __shared__ __align__(128) unsigned char stageA[STAGE_BYTES]; // [tab][p] gather4 results
    __shared__ __align__(128) unsigned char stageB[STAGE_BYTES]; // [p][tab] store layout
    __shared__ __align__(8)  unsigned long long mbar;

    const int tid = threadIdx.x;
    const uint32_t stA = smem_u32(stageA);
    const uint32_t mbar_a = smem_u32(&mbar);

    if (tid == 0) {
        asm volatile("mbarrier.init.shared.b64 [%0], 1;" :: "r"(mbar_a) : "memory");
    }
    __syncthreads();

    const int base = blockIdx.x * P4;

    uint64_t pol_ef, pol_el;
    asm("createpolicy.fractional.L2::evict_first.b64 %0, 1.0;" : "=l"(pol_ef));
    asm("createpolicy.fractional.L2::evict_last.b64 %0, 1.0;"  : "=l"(pol_el));

    if (tid == 0) {
        asm volatile("mbarrier.arrive.expect_tx.shared.b64 _, [%0], %1;"
                     :: "r"(mbar_a), "r"((int)STAGE_BYTES) : "memory");
    }

    // 16 threads: one table each; hash 4 positions, one gather4 request
    if (tid < NTAB) {
        const int tab  = tid;
        const int head = tab & 7;
        const unsigned long long sd0 = (unsigned int)__ldg(seeds + head);
        const unsigned long long sd1 = (unsigned int)__ldg(seeds + 8 + head);
        const unsigned long long sd2 = (unsigned int)__ldg(seeds + 16 + head);
        const unsigned long long ts  = c_sizes[tab];

        int y[P4];
        #pragma unroll
        for (int p = 0; p < P4; p++) {
            const int pos = base + p;
            const int s   = pos & (SEQ - 1);
            const unsigned long long id0 = (unsigned int)__ldg(ids + pos);
            const unsigned long long id1 =
                (s >= 1) ? (unsigned long long)(unsigned int)__ldg(ids + pos - 1) : 0ull;
            unsigned long long h;
            if (tab < 8) {
                h = (id1 * sd0) ^ (id0 * sd1);
            } else {
                const unsigned long long id2 =
                    (s >= 2) ? (unsigned long long)(unsigned int)__ldg(ids + pos - 2) : 0ull;
                h = (id2 * sd0) ^ (id1 * sd1) ^ (id0 * sd2);
            }
            y[p] = (int)(unsigned int)(h % ts);
        }

        const uint32_t dst = stA + (uint32_t)tab * TAB_STRIDE;
        asm volatile(
            "cp.async.bulk.tensor.2d.shared::cta.global.tile::gather4"
            ".mbarrier::complete_tx::bytes.L2::cache_hint "
            "[%0], [%1, {%2, %3, %4, %5, %6}], [%7], %8;"
            :: "r"(dst), "l"(&maps.m[tab]),
               "r"(0), "r"(y[0]), "r"(y[1]), "r"(y[2]), "r"(y[3]),
               "r"(mbar_a), "l"(pol_el)
            : "memory");
    }

    // all threads wait for all 16 gather4 completions (20480 bytes)
    asm volatile(
        "{\n\t"
        ".reg .pred P1;\n\t"
        "W_%=:\n\t"
        "mbarrier.try_wait.parity.shared.b64 P1, [%0], 0, 0x989680;\n\t"
        "@P1 bra.uni D_%=;\n\t"
        "bra.uni W_%=;\n\t"
        "D_%=:\n\t"
        "}"
        :: "r"(mbar_a) : "memory");

    // transpose [tab][p][320B] -> [p][tab][320B]
    // warp w handles tabs [4w, 4w+4); lanes read consecutive float4 (conflict-free)
    {
        const int w = tid >> 5, l = tid & 31;
        #pragma unroll
        for (int tt = 0; tt < 4; tt++) {
            const int tab = w * 4 + tt;
            #pragma unroll
            for (int j = 0; j < 3; j++) {
                const int f = j * 32 + l;                 // float4 index within tab block
                if (f < P4 * (ROW_BYTES / 16)) {          // < 80
                    const float4 v = *(const float4*)(stageA + tab * TAB_STRIDE + f * 16);
                    const int p = f / (ROW_BYTES / 16);   // /20
                    const int q = f - p * (ROW_BYTES / 16);
                    *(float4*)(stageB + p * POS_BYTES + tab * ROW_BYTES + q * 16) = v;
                }
            }
        }
    }
    __syncthreads();

    // single contiguous 20KB bulk store for the 4 positions
    if (tid == 0) {
        asm volatile("fence.proxy.async.shared::cta;" ::: "memory");
        char* gdst = (char*)out + (size_t)base * POS_BYTES;
        asm volatile(
            "cp.async.bulk.global.shared::cta.bulk_group.L2::cache_hint "
            "[%0], [%1], %2, %3;"
            :: "l"(gdst), "r"(smem_u32(stageB)), "r"((int)STAGE_BYTES), "l"(pol_ef)
            : "memory");
        asm volatile("cp.async.bulk.commit_group;" ::: "memory");
        asm volatile("cp.async.bulk.wait_group.read 0;" ::: "memory");
    }
}

// ==================== fallback: R7 (50.2us known-good) ====================
#define FB_P       4
#define FB_THREADS (FB_P * NTAB)             // 64
#define FB_STAGE   (FB_P * POS_BYTES)        // 20480
#define FB_BLOCKS  (NPOS / FB_P)             // 8192

__global__ __launch_bounds__(FB_THREADS) void engram_fb_kernel(
    const int* __restrict__ ids,
    const int* __restrict__ seeds,
    Tables tp,
    float* __restrict__ out)
{
    __shared__ __align__(16) unsigned char stage[FB_STAGE];
    __shared__ __align__(8)  unsigned long long mbar[FB_P];

    const int tid = threadIdx.x;
    const uint32_t stage_a = smem_u32(stage);
    const uint32_t mbar_a0 = smem_u32(mbar);

    if (tid < FB_P) {
        asm volatile("mbarrier.init.shared.b64 [%0], 1;"
                     :: "r"(mbar_a0 + tid * 8) : "memory");
    }
    __syncthreads();

    const int p    = tid >> 4;
    const int tab  = tid & 15;
    const int head = tab & 7;
    const int pos  = blockIdx.x * FB_P + p;
    const int s    = pos & (SEQ - 1);
    const uint32_t my_mbar = mbar_a0 + p * 8;

    uint64_t pol_ef, pol_el;
    asm("createpolicy.fractional.L2::evict_first.b64 %0, 1.0;" : "=l"(pol_ef));
    asm("createpolicy.fractional.L2::evict_last.b64 %0, 1.0;"  : "=l"(pol_el));

    const unsigned long long id0 = (unsigned int)__ldg(ids + pos);
    const unsigned long long id1 =
        (s >= 1) ? (unsigned long long)(unsigned int)__ldg(ids + pos - 1) : 0ull;

    unsigned long long h;
    if (tab < 8) {
        h = (id1 * (unsigned long long)(unsigned int)__ldg(seeds + head))
          ^ (id0 * (unsigned long long)(unsigned int)__ldg(seeds + 8 + head));
    } else {
        const unsigned long long id2 =
            (s >= 2) ? (unsigned long long)(unsigned int)__ldg(ids + pos - 2) : 0ull;
        h = (id2 * (unsigned long long)(unsigned int)__ldg(seeds + head))
          ^ (id1 * (unsigned long long)(unsigned int)__ldg(seeds + 8 + head))
          ^ (id0 * (unsigned long long)(unsigned int)__ldg(seeds + 16 + head));
    }
    const unsigned int idx = (unsigned int)(h % (unsigned long long)c_sizes[tab]);

    if (tab == 0) {
        asm volatile("mbarrier.arrive.expect_tx.shared.b64 _, [%0], %1;"
                     :: "r"(my_mbar), "r"((int)POS_BYTES) : "memory");
    }
    {
        const char*    src = (const char*)tp.t[tab] + (size_t)idx * ROW_BYTES;
        const uint32_t dst = stage_a + (uint32_t)tid * ROW_BYTES;
        asm volatile(
            "cp.async.bulk.shared::cta.global.mbarrier::complete_tx::bytes.L2::cache_hint "
            "[%0], [%1], %2, [%3], %4;"
            :: "r"(dst), "l"(src), "r"((int)ROW_BYTES), "r"(my_mbar), "l"(pol_el)
            : "memory");
    }

    if (tab == 0) {
        asm volatile(
            "{\n\t"
            ".reg .pred P1;\n\t"
            "W_%=:\n\t"
            "mbarrier.try_wait.parity.shared.b64 P1, [%0], 0, 0x989680;\n\t"
            "@P1 bra.uni D_%=;\n\t"
            "bra.uni W_%=;\n\t"
            "D_%=:\n\t"
            "}"
            :: "r"(my_mbar) : "memory");

        char* gdst = (char*)out + (size_t)pos * POS_BYTES;
        asm volatile(
            "cp.async.bulk.global.shared::cta.bulk_group.L2::cache_hint "
            "[%0], [%1], %2, %3;"
            :: "l"(gdst), "r"(stage_a + (uint32_t)p * POS_BYTES), "r"((int)POS_BYTES),
               "l"(pol_ef)
            : "memory");
        asm volatile("cp.async.bulk.commit_group;" ::: "memory");
        asm volatile("cp.async.bulk.wait_group.read 0;" ::: "memory");
    }
}

// ==================== host ====================
typedef CUresult (*PFN_encodeTiled)(
    CUtensorMap*, CUtensorMapDataType, cuuint32_t, void*,
    const cuuint64_t*, const cuuint64_t*, const cuuint32_t*, const cuuint32_t*,
    CUtensorMapInterleave, CUtensorMapSwizzle, CUtensorMapL2promotion,
    CUtensorMapFloatOOBfill);

extern "C" void kernel_launch(void* const* d_in, const int* in_sizes, int n_in,
                              void* d_out, int out_size)
{
    const int* ids   = (const int*)d_in[0];
    const int* seeds = (const int*)d_in[1];

    bool ok = false;
    TMaps maps;
    void* fp = nullptr;
    cudaDriverEntryPointQueryResult qres;
    if (cudaGetDriverEntryPointByVersion("cuTensorMapEncodeTiled", &fp, 12000,
                                         cudaEnableDefault, &qres) == cudaSuccess
        && fp != nullptr) {
        PFN_encodeTiled enc = (PFN_encodeTiled)fp;
        ok = true;
        for (int t = 0; t < 16 && ok; t++) {
            cuuint64_t dims[2]    = {(cuuint64_t)SLOT, (cuuint64_t)h_sizes[t]};
            cuuint64_t strides[1] = {(cuuint64_t)ROW_BYTES};
            cuuint32_t box[2]     = {(cuuint32_t)SLOT, 1u};
            cuuint32_t estr[2]    = {1u, 1u};
            CUresult r = enc(&maps.m[t], CU_TENSOR_MAP_DATA_TYPE_FLOAT32, 2,
                             (void*)d_in[2 + t], dims, strides, box, estr,
                             CU_TENSOR_MAP_INTERLEAVE_NONE,
                             CU_TENSOR_MAP_SWIZZLE_NONE,
                             CU_TENSOR_MAP_L2_PROMOTION_L2_128B,
                             CU_TENSOR_MAP_FLOAT_OOB_FILL_NONE);
            if (r != CUDA_SUCCESS) ok = false;
        }
    }

    if (ok) {
        engram_g4_kernel<<<G4_BLOCKS, G4_THREADS>>>(ids, seeds, maps, (float*)d_out);
    } else {
        Tables tp;
        for (int i = 0; i < 16; i++) tp.t[i] = (const float*)d_in[2 + i];
        engram_fb_kernel<<<FB_BLOCKS, FB_THREADS>>>(ids, seeds, tp, (float*)d_out);
    }
}

// round 13
// speedup vs baseline: 1.2018x; 1.1760x over previous
#include <cuda_runtime.h>
#include <stdint.h>

#define SEQ   4096
#define NPOS  32768
#define SLOT  80
#define ROW_BYTES (SLOT * 4)                 // 320
#define NTAB  16
#define POS_BYTES (NTAB * ROW_BYTES)         // 5120 per position
#define P     4                              // positions per block
#define THREADS (P * NTAB)                   // 64
#define STAGE_BYTES (P * POS_BYTES)          // 20480
#define NBLOCKS (NPOS / P)                   // 8192

// table sizes: 8 x n=2 then 8 x n=3
__constant__ unsigned int c_sizes[16] = {
    6619u, 6637u, 6653u, 6659u, 6661u, 6673u, 6679u, 6689u,
    65521u, 65537u, 65539u, 65543u, 65551u, 65557u, 65563u, 65579u
};

struct Tables { const float* t[16]; };

__device__ __forceinline__ uint32_t smem_u32(const void* p) {
    uint32_t a;
    asm("{ .reg .u64 tmp; cvta.to.shared.u64 tmp, %1; cvt.u32.u64 %0, tmp; }"
        : "=r"(a) : "l"(p));
    return a;
}

__global__ __launch_bounds__(THREADS) void engram_kernel(
    const int* __restrict__ ids,      // [B, S] int32
    const int* __restrict__ seeds,    // [3, 8] int32
    Tables tp,
    float* __restrict__ out)          // [B, S, 1280] fp32
{
    __shared__ __align__(16) unsigned char stage[STAGE_BYTES];
    __shared__ __align__(8)  unsigned long long mbar[P];

    const int tid = threadIdx.x;
    const uint32_t stage_a = smem_u32(stage);
    const uint32_t mbar_a0 = smem_u32(mbar);

    if (tid < P) {
        asm volatile("mbarrier.init.shared.b64 [%0], 1;"
                     :: "r"(mbar_a0 + tid * 8) : "memory");
    }
    __syncthreads();

    const int p    = tid >> 4;           // position within block
    const int tab  = tid & 15;           // table index
    const int head = tab & 7;
    const int pos  = blockIdx.x * P + p;
    const int s    = pos & (SEQ - 1);
    const uint32_t my_mbar = mbar_a0 + p * 8;

    // L2 policies:
    //  - output stores: evict_first (streaming)
    //  - PINNED loads (n2 tables + n3 tables 0-3): evict_last. Pinned touched
    //    set ~= 17MB + 33MB = 50MB — sized to FIT the evict_last capacity so
    //    it can persist across graph replays (steady-state reads = L2 hits).
    //  - remaining n3 tables (12-15): evict_first (low re-hit; keep them from
    //    competing with the pinned set)
    uint64_t pol_ef, pol_el;
    asm("createpolicy.fractional.L2::evict_first.b64 %0, 1.0;" : "=l"(pol_ef));
    asm("createpolicy.fractional.L2::evict_last.b64 %0, 1.0;"  : "=l"(pol_el));
    const uint64_t ld_pol = (tab < 12) ? pol_el : pol_ef;

    // hash
    const unsigned long long id0 = (unsigned int)__ldg(ids + pos);
    const unsigned long long id1 =
        (s >= 1) ? (unsigned long long)(unsigned int)__ldg(ids + pos - 1) : 0ull;

    unsigned long long h;
    if (tab < 8) {
        h = (id1 * (unsigned long long)(unsigned int)__ldg(seeds + head))
          ^ (id0 * (unsigned long long)(unsigned int)__ldg(seeds + 8 + head));
    } else {
        const unsigned long long id2 =
            (s >= 2) ? (unsigned long long)(unsigned int)__ldg(ids + pos - 2) : 0ull;
        h = (id2 * (unsigned long long)(unsigned int)__ldg(seeds + head))
          ^ (id1 * (unsigned long long)(unsigned int)__ldg(seeds + 8 + head))
          ^ (id0 * (unsigned long long)(unsigned int)__ldg(seeds + 16 + head));
    }
    const unsigned int idx = (unsigned int)(h % (unsigned long long)c_sizes[tab]);

    // drain thread posts the expected byte count for this position's barrier
    if (tab == 0) {
        asm volatile("mbarrier.arrive.expect_tx.shared.b64 _, [%0], %1;"
                     :: "r"(my_mbar), "r"((int)POS_BYTES) : "memory");
    }
    // all 16 threads of this position issue their row copy to the position barrier
    {
        const char*    src = (const char*)tp.t[tab] + (size_t)idx * ROW_BYTES;
        const uint32_t dst = stage_a + (uint32_t)tid * ROW_BYTES;  // (p*16+tab)*320
        asm volatile(
            "cp.async.bulk.shared::cta.global.mbarrier::complete_tx::bytes.L2::cache_hint "
            "[%0], [%1], %2, [%3], %4;"
            :: "r"(dst), "l"(src), "r"((int)ROW_BYTES), "r"(my_mbar), "l"(ld_pol)
            : "memory");
    }

    // per-position drain: as soon as this position's 5120B are in smem,
    // issue one contiguous 5KB bulk store. P independent drain threads.
    if (tab == 0) {
        asm volatile(
            "{\n\t"
            ".reg .pred P1;\n\t"
            "W_%=:\n\t"
            "mbarrier.try_wait.parity.shared.b64 P1, [%0], 0, 0x989680;\n\t"
            "@P1 bra.uni D_%=;\n\t"
            "bra.uni W_%=;\n\t"
            "D_%=:\n\t"
            "}"
            :: "r"(my_mbar) : "memory");

        char* gdst = (char*)out + (size_t)pos * POS_BYTES;
        asm volatile(
            "cp.async.bulk.global.shared::cta.bulk_group.L2::cache_hint "
            "[%0], [%1], %2, %3;"
            :: "l"(gdst), "r"(stage_a + (uint32_t)p * POS_BYTES), "r"((int)POS_BYTES),
               "l"(pol_ef)
            : "memory");
        asm volatile("cp.async.bulk.commit_group;" ::: "memory");
        // only wait until the store has READ smem (CTA slot may then recycle);
        // global write completion is guaranteed by kernel-end semantics.
        asm volatile("cp.async.bulk.wait_group.read 0;" ::: "memory");
    }
}

extern "C" void kernel_launch(void* const* d_in, const int* in_sizes, int n_in,
                              void* d_out, int out_size)
{
    const int* ids   = (const int*)d_in[0];
    const int* seeds = (const int*)d_in[1];

    Tables tp;
    #pragma unroll
    for (int i = 0; i < 16; i++) tp.t[i] = (const float*)d_in[2 + i];

    engram_kernel<<<NBLOCKS, THREADS>>>(ids, seeds, tp, (float*)d_out);
}

// round 14
// speedup vs baseline: 1.2781x; 1.0635x over previous
#include <cuda_runtime.h>
#include <cuda.h>
#include <stdint.h>

#define SEQ   4096
#define NPOS  32768
#define SLOT  80
#define ROW_BYTES (SLOT * 4)                 // 320
#define NTAB  16
#define POS_BYTES (NTAB * ROW_BYTES)         // 5120
#define P4    4                              // positions per block
#define TAB_STRIDE (P4 * ROW_BYTES)          // 1280 per gather4 result
#define STAGE_BYTES (NTAB * TAB_STRIDE)      // 20480 ([tab][p] layout)
#define G4_BLOCKS (NPOS / P4)                // 8192
#define G4_THREADS 128
#define WARP_BYTES (4 * TAB_STRIDE)          // 5120 per warp (4 tables)

__constant__ unsigned int c_sizes[16] = {
    6619u, 6637u, 6653u, 6659u, 6661u, 6673u, 6679u, 6689u,
    65521u, 65537u, 65539u, 65543u, 65551u, 65557u, 65563u, 65579u
};

static const unsigned int h_sizes[16] = {
    6619u, 6637u, 6653u, 6659u, 6661u, 6673u, 6679u, 6689u,
    65521u, 65537u, 65539u, 65543u, 65551u, 65557u, 65563u, 65579u
};

struct Tables { const float* t[16]; };
struct TMaps  { CUtensorMap m[16]; };

__device__ __forceinline__ uint32_t smem_u32(const void* p) {
    uint32_t a;
    asm("{ .reg .u64 tmp; cvta.to.shared.u64 tmp, %1; cvt.u32.u64 %0, tmp; }"
        : "=r"(a) : "l"(p));
    return a;
}

// ============ gather4 reads, warp-independent STG drain (no transpose) ============
__global__ __launch_bounds__(G4_THREADS) void engram_g4_kernel(
    const int* __restrict__ ids,
    const int* __restrict__ seeds,
    const __grid_constant__ TMaps maps,
    float* __restrict__ out)
{
    __shared__ __align__(128) unsigned char stage[STAGE_BYTES];  // [tab][p][320B]
    __shared__ __align__(8)  unsigned long long mbar[4];         // one per warp

    const int tid  = threadIdx.x;
    const int w    = tid >> 5;
    const int lane = tid & 31;
    const uint32_t stage_a = smem_u32(stage);
    const uint32_t my_mbar = smem_u32(&mbar[w]);

    if (lane == 0) {
        asm volatile("mbarrier.init.shared.b64 [%0], 1;" :: "r"(my_mbar) : "memory");
        asm volatile("mbarrier.arrive.expect_tx.shared.b64 _, [%0], %1;"
                     :: "r"(my_mbar), "r"((int)WARP_BYTES) : "memory");
    }
    __syncwarp();

    const int base = blockIdx.x * P4;
    const int t0   = w * 4;                   // this warp's first table

    uint64_t pol_el;
    asm("createpolicy.fractional.L2::evict_last.b64 %0, 1.0;" : "=l"(pol_el));

    // lanes 0-15: lane l -> table t0 + (l>>2), position l&3: compute hash index
    unsigned int idx = 0;
    if (lane < 16) {
        const int tab  = t0 + (lane >> 2);
        const int p    = lane & 3;
        const int head = tab & 7;
        const int pos  = base + p;
        const int s    = pos & (SEQ - 1);

        const unsigned long long id0 = (unsigned int)__ldg(ids + pos);
        const unsigned long long id1 =
            (s >= 1) ? (unsigned long long)(unsigned int)__ldg(ids + pos - 1) : 0ull;

        unsigned long long h;
        if (tab < 8) {
            h = (id1 * (unsigned long long)(unsigned int)__ldg(seeds + head))
              ^ (id0 * (unsigned long long)(unsigned int)__ldg(seeds + 8 + head));
        } else {
            const unsigned long long id2 =
                (s >= 2) ? (unsigned long long)(unsigned int)__ldg(ids + pos - 2) : 0ull;
            h = (id2 * (unsigned long long)(unsigned int)__ldg(seeds + head))
              ^ (id1 * (unsigned long long)(unsigned int)__ldg(seeds + 8 + head))
              ^ (id0 * (unsigned long long)(unsigned int)__ldg(seeds + 16 + head));
        }
        idx = (unsigned int)(h % (unsigned long long)c_sizes[tab]);
    }

    // collect 4 position-indices into the group leader (lanes 0,4,8,12)
    const unsigned y0 = __shfl_sync(0xFFFFFFFFu, idx, (lane & 12) | 0);
    const unsigned y1 = __shfl_sync(0xFFFFFFFFu, idx, (lane & 12) | 1);
    const unsigned y2 = __shfl_sync(0xFFFFFFFFu, idx, (lane & 12) | 2);
    const unsigned y3 = __shfl_sync(0xFFFFFFFFu, idx, (lane & 12) | 3);

    if (lane < 16 && (lane & 3) == 0) {
        const int tab = t0 + (lane >> 2);
        const uint32_t dst = stage_a + (uint32_t)tab * TAB_STRIDE;
        asm volatile(
            "cp.async.bulk.tensor.2d.shared::cta.global.tile::gather4"
            ".mbarrier::complete_tx::bytes.L2::cache_hint "
            "[%0], [%1, {%2, %3, %4, %5, %6}], [%7], %8;"
            :: "r"(dst), "l"(&maps.m[tab]),
               "r"(0), "r"((int)y0), "r"((int)y1), "r"((int)y2), "r"((int)y3),
               "r"(my_mbar), "l"(pol_el)
            : "memory");
    }

    // warp-local wait (acquire) for its own 5120B
    asm volatile(
        "{\n\t"
        ".reg .pred P1;\n\t"
        "W_%=:\n\t"
        "mbarrier.try_wait.parity.acquire.cta.shared::cta.b64 P1, [%0], 0, 0x989680;\n\t"
        "@P1 bra.uni D_%=;\n\t"
        "bra.uni W_%=;\n\t"
        "D_%=:\n\t"
        "}"
        :: "r"(my_mbar) : "memory");

    // drain: 4 tables x 4 positions x 20 float4 = 320 float4 per warp,
    // smem [tab][p][q] -> gmem (base+p)*5120 + tab*320 + q*16, streaming stores
    const unsigned char* wsrc = stage + (size_t)t0 * TAB_STRIDE;
    float* gbase = out + (size_t)base * (POS_BYTES / 4) + (size_t)t0 * SLOT;
    #pragma unroll
    for (int i = 0; i < 10; i++) {
        const int f   = i * 32 + lane;        // 0..319
        const int tt  = f / 80;               // table within warp group
        const int rem = f - tt * 80;
        const int p   = rem / 20;             // position
        const int q   = rem - p * 20;         // float4 within row
        const float4 v = *(const float4*)(wsrc + (tt * P4 + p) * ROW_BYTES + q * 16);
        __stcs((float4*)(gbase + (size_t)p * (POS_BYTES / 4) + tt * SLOT + q * 4), v);
    }
}

// ==================== fallback: R7 (50.2us known-good) ====================
#define FB_P       4
#define FB_THREADS (FB_P * NTAB)             // 64
#define FB_STAGE   (FB_P * POS_BYTES)        // 20480
#define FB_BLOCKS  (NPOS / FB_P)             // 8192

__global__ __launch_bounds__(FB_THREADS) void engram_fb_kernel(
    const int* __restrict__ ids,
    const int* __restrict__ seeds,
    Tables tp,
    float* __restrict__ out)
{
    __shared__ __align__(16) unsigned char stage[FB_STAGE];
    __shared__ __align__(8)  unsigned long long mbar[FB_P];

    const int tid = threadIdx.x;
    const uint32_t stage_a = smem_u32(stage);
    const uint32_t mbar_a0 = smem_u32(mbar);

    if (tid < FB_P) {
        asm volatile("mbarrier.init.shared.b64 [%0], 1;"
                     :: "r"(mbar_a0 + tid * 8) : "memory");
    }
    __syncthreads();

    const int p    = tid >> 4;
    const int tab  = tid & 15;
    const int head = tab & 7;
    const int pos  = blockIdx.x * FB_P + p;
    const int s    = pos & (SEQ - 1);
    const uint32_t my_mbar = mbar_a0 + p * 8;

    uint64_t pol_ef, pol_el;
    asm("createpolicy.fractional.L2::evict_first.b64 %0, 1.0;" : "=l"(pol_ef));
    asm("createpolicy.fractional.L2::evict_last.b64 %0, 1.0;"  : "=l"(pol_el));

    const unsigned long long id0 = (unsigned int)__ldg(ids + pos);
    const unsigned long long id1 =
        (s >= 1) ? (unsigned long long)(unsigned int)__ldg(ids + pos - 1) : 0ull;

    unsigned long long h;
    if (tab < 8) {
        h = (id1 * (unsigned long long)(unsigned int)__ldg(seeds + head))
          ^ (id0 * (unsigned long long)(unsigned int)__ldg(seeds + 8 + head));
    } else {
        const unsigned long long id2 =
            (s >= 2) ? (unsigned long long)(unsigned int)__ldg(ids + pos - 2) : 0ull;
        h = (id2 * (unsigned long long)(unsigned int)__ldg(seeds + head))
          ^ (id1 * (unsigned long long)(unsigned int)__ldg(seeds + 8 + head))
          ^ (id0 * (unsigned long long)(unsigned int)__ldg(seeds + 16 + head));
    }
    const unsigned int idx = (unsigned int)(h % (unsigned long long)c_sizes[tab]);

    if (tab == 0) {
        asm volatile("mbarrier.arrive.expect_tx.shared.b64 _, [%0], %1;"
                     :: "r"(my_mbar), "r"((int)POS_BYTES) : "memory");
    }
    {
        const char*    src = (const char*)tp.t[tab] + (size_t)idx * ROW_BYTES;
        const uint32_t dst = stage_a + (uint32_t)tid * ROW_BYTES;
        asm volatile(
            "cp.async.bulk.shared::cta.global.mbarrier::complete_tx::bytes.L2::cache_hint "
            "[%0], [%1], %2, [%3], %4;"
            :: "r"(dst), "l"(src), "r"((int)ROW_BYTES), "r"(my_mbar), "l"(pol_el)
            : "memory");
    }

    if (tab == 0) {
        asm volatile(
            "{\n\t"
            ".reg .pred P1;\n\t"
            "W_%=:\n\t"
            "mbarrier.try_wait.parity.shared.b64 P1, [%0], 0, 0x989680;\n\t"
            "@P1 bra.uni D_%=;\n\t"
            "bra.uni W_%=;\n\t"
            "D_%=:\n\t"
            "}"
            :: "r"(my_mbar) : "memory");

        char* gdst = (char*)out + (size_t)pos * POS_BYTES;
        asm volatile(
            "cp.async.bulk.global.shared::cta.bulk_group.L2::cache_hint "
            "[%0], [%1], %2, %3;"
            :: "l"(gdst), "r"(stage_a + (uint32_t)p * POS_BYTES), "r"((int)POS_BYTES),
               "l"(pol_ef)
            : "memory");
        asm volatile("cp.async.bulk.commit_group;" ::: "memory");
        asm volatile("cp.async.bulk.wait_group.read 0;" ::: "memory");
    }
}

// ==================== host ====================
typedef CUresult (*PFN_encodeTiled)(
    CUtensorMap*, CUtensorMapDataType, cuuint32_t, void*,
    const cuuint64_t*, const cuuint64_t*, const cuuint32_t*, const cuuint32_t*,
    CUtensorMapInterleave, CUtensorMapSwizzle, CUtensorMapL2promotion,
    CUtensorMapFloatOOBfill);

extern "C" void kernel_launch(void* const* d_in, const int* in_sizes, int n_in,
                              void* d_out, int out_size)
{
    const int* ids   = (const int*)d_in[0];
    const int* seeds = (const int*)d_in[1];

    bool ok = false;
    TMaps maps;
    void* fp = nullptr;
    cudaDriverEntryPointQueryResult qres;
    if (cudaGetDriverEntryPointByVersion("cuTensorMapEncodeTiled", &fp, 12000,
                                         cudaEnableDefault, &qres) == cudaSuccess
        && fp != nullptr) {
        PFN_encodeTiled enc = (PFN_encodeTiled)fp;
        ok = true;
        for (int t = 0; t < 16 && ok; t++) {
            cuuint64_t dims[2]    = {(cuuint64_t)SLOT, (cuuint64_t)h_sizes[t]};
            cuuint64_t strides[1] = {(cuuint64_t)ROW_BYTES};
            cuuint32_t box[2]     = {(cuuint32_t)SLOT, 1u};
            cuuint32_t estr[2]    = {1u, 1u};
            CUresult r = enc(&maps.m[t], CU_TENSOR_MAP_DATA_TYPE_FLOAT32, 2,
                             (void*)d_in[2 + t], dims, strides, box, estr,
                             CU_TENSOR_MAP_INTERLEAVE_NONE,
                             CU_TENSOR_MAP_SWIZZLE_NONE,
                             CU_TENSOR_MAP_L2_PROMOTION_L2_128B,
                             CU_TENSOR_MAP_FLOAT_OOB_FILL_NONE);
            if (r != CUDA_SUCCESS) ok = false;
        }
    }

    if (ok) {
        engram_g4_kernel<<<G4_BLOCKS, G4_THREADS>>>(ids, seeds, maps, (float*)d_out);
    } else {
        Tables tp;
        for (int i = 0; i < 16; i++) tp.t[i] = (const float*)d_in[2 + i];
        engram_fb_kernel<<<FB_BLOCKS, FB_THREADS>>>(ids, seeds, tp, (float*)d_out);
    }
}

// round 15
// speedup vs baseline: 1.2849x; 1.0054x over previous
#include <cuda_runtime.h>
#include <cuda.h>
#include <stdint.h>

#define SEQ   4096
#define NPOS  32768
#define SLOT  80
#define ROW_BYTES (SLOT * 4)                 // 320
#define NTAB  16
#define POS_BYTES (NTAB * ROW_BYTES)         // 5120
#define P4    4                              // positions per chunk
#define TAB_STRIDE (P4 * ROW_BYTES)          // 1280 per gather4 result
#define WARP_BYTES (4 * TAB_STRIDE)          // 5120 per warp-chunk (4 tables)
#define CHUNKS 4                             // chunks per block (pipelined)
#define POS_PER_BLOCK (P4 * CHUNKS)          // 16
#define G4_BLOCKS (NPOS / POS_PER_BLOCK)     // 2048
#define G4_THREADS 128

__constant__ unsigned int c_sizes[16] = {
    6619u, 6637u, 6653u, 6659u, 6661u, 6673u, 6679u, 6689u,
    65521u, 65537u, 65539u, 65543u, 65551u, 65557u, 65563u, 65579u
};

static const unsigned int h_sizes[16] = {
    6619u, 6637u, 6653u, 6659u, 6661u, 6673u, 6679u, 6689u,
    65521u, 65537u, 65539u, 65543u, 65551u, 65557u, 65563u, 65579u
};

struct Tables { const float* t[16]; };
struct TMaps  { CUtensorMap m[16]; };

__device__ __forceinline__ uint32_t smem_u32(const void* p) {
    uint32_t a;
    asm("{ .reg .u64 tmp; cvta.to.shared.u64 tmp, %1; cvt.u32.u64 %0, tmp; }"
        : "=r"(a) : "l"(p));
    return a;
}

__device__ __forceinline__ void mbar_wait(uint32_t mbar, unsigned phase) {
    asm volatile(
        "{\n\t"
        ".reg .pred P1;\n\t"
        "W_%=:\n\t"
        "mbarrier.try_wait.parity.acquire.cta.shared::cta.b64 P1, [%0], %1, 0x989680;\n\t"
        "@P1 bra.uni D_%=;\n\t"
        "bra.uni W_%=;\n\t"
        "D_%=:\n\t"
        "}"
        :: "r"(mbar), "r"(phase) : "memory");
}

// drain one chunk: 4 tables x 4 positions x 20 float4 per warp -> coalesced STG
__device__ __forceinline__ void drain_chunk(
    const unsigned char* wsrc, float* __restrict__ out,
    int posbase, int t0, int lane)
{
    float* gbase = out + (size_t)posbase * (POS_BYTES / 4) + (size_t)t0 * SLOT;
    #pragma unroll
    for (int i = 0; i < 10; i++) {
        const int f   = i * 32 + lane;        // 0..319
        const int tt  = f / 80;
        const int rem = f - tt * 80;
        const int p   = rem / 20;
        const int q   = rem - p * 20;
        const float4 v = *(const float4*)(wsrc + (tt * P4 + p) * ROW_BYTES + q * 16);
        __stcs((float4*)(gbase + (size_t)p * (POS_BYTES / 4) + tt * SLOT + q * 4), v);
    }
}

// ======== pipelined gather4 (depth-2 per warp), warp-independent STG drain ========
__global__ __launch_bounds__(G4_THREADS) void engram_g4_kernel(
    const int* __restrict__ ids,
    const int* __restrict__ seeds,
    const __grid_constant__ TMaps maps,
    float* __restrict__ out)
{
    __shared__ __align__(128) unsigned char stage[4][2][WARP_BYTES]; // [warp][buf]
    __shared__ __align__(8)  unsigned long long mbar[4][2];

    const int tid  = threadIdx.x;
    const int w    = tid >> 5;
    const int lane = tid & 31;
    const uint32_t mb0 = smem_u32(&mbar[w][0]);
    const uint32_t mb1 = smem_u32(&mbar[w][1]);

    if (lane == 0) {
        asm volatile("mbarrier.init.shared.b64 [%0], 1;" :: "r"(mb0) : "memory");
        asm volatile("mbarrier.init.shared.b64 [%0], 1;" :: "r"(mb1) : "memory");
    }
    __syncwarp();

    const int blockbase = blockIdx.x * POS_PER_BLOCK;
    const int t0  = w * 4;                    // this warp's first table
    const int tab = t0 + (lane >> 2);         // hash-lane table (lanes 0-15)
    const int head = tab & 7;

    // hoist per-lane constants
    const unsigned long long sd0 = (unsigned int)__ldg(seeds + head);
    const unsigned long long sd1 = (unsigned int)__ldg(seeds + 8 + head);
    const unsigned long long sd2 = (unsigned int)__ldg(seeds + 16 + head);
    const unsigned long long ts  = c_sizes[tab];

    uint64_t pol_el;
    asm("createpolicy.fractional.L2::evict_last.b64 %0, 1.0;" : "=l"(pol_el));

    #pragma unroll
    for (int c = 0; c < CHUNKS; c++) {
        const int posbase = blockbase + c * P4;
        const uint32_t mb  = (c & 1) ? mb1 : mb0;
        const uint32_t dst0 = smem_u32(&stage[w][c & 1][0]);

        // hash: lanes 0-15 -> (table, position)
        unsigned int idx = 0;
        if (lane < 16) {
            const int pos = posbase + (lane & 3);
            const int s   = pos & (SEQ - 1);
            const unsigned long long id0 = (unsigned int)__ldg(ids + pos);
            const unsigned long long id1 =
                (s >= 1) ? (unsigned long long)(unsigned int)__ldg(ids + pos - 1) : 0ull;
            unsigned long long h;
            if (tab < 8) {
                h = (id1 * sd0) ^ (id0 * sd1);
            } else {
                const unsigned long long id2 =
                    (s >= 2) ? (unsigned long long)(unsigned int)__ldg(ids + pos - 2) : 0ull;
                h = (id2 * sd0) ^ (id1 * sd1) ^ (id0 * sd2);
            }
            idx = (unsigned int)(h % ts);
        }
        const unsigned y0 = __shfl_sync(0xFFFFFFFFu, idx, (lane & 12) | 0);
        const unsigned y1 = __shfl_sync(0xFFFFFFFFu, idx, (lane & 12) | 1);
        const unsigned y2 = __shfl_sync(0xFFFFFFFFu, idx, (lane & 12) | 2);
        const unsigned y3 = __shfl_sync(0xFFFFFFFFu, idx, (lane & 12) | 3);

        if (lane == 0) {
            asm volatile("mbarrier.arrive.expect_tx.shared.b64 _, [%0], %1;"
                         :: "r"(mb), "r"((int)WARP_BYTES) : "memory");
        }
        __syncwarp();
        if (lane < 16 && (lane & 3) == 0) {
            const int mytab = t0 + (lane >> 2);
            const uint32_t dst = dst0 + (uint32_t)(lane >> 2) * TAB_STRIDE;
            asm volatile(
                "cp.async.bulk.tensor.2d.shared::cta.global.tile::gather4"
                ".mbarrier::complete_tx::bytes.L2::cache_hint "
                "[%0], [%1, {%2, %3, %4, %5, %6}], [%7], %8;"
                :: "r"(dst), "l"(&maps.m[mytab]),
                   "r"(0), "r"((int)y0), "r"((int)y1), "r"((int)y2), "r"((int)y3),
                   "r"(mb), "l"(pol_el)
                : "memory");
        }

        // drain PREVIOUS chunk while this one is in flight
        if (c >= 1) {
            const int cp = c - 1;
            mbar_wait((cp & 1) ? mb1 : mb0, (unsigned)((cp >> 1) & 1));
            drain_chunk(&stage[w][cp & 1][0], out, blockbase + cp * P4, t0, lane);
        }
    }

    // epilogue: drain the last chunk
    {
        const int cp = CHUNKS - 1;
        mbar_wait((cp & 1) ? mb1 : mb0, (unsigned)((cp >> 1) & 1));
        drain_chunk(&stage[w][cp & 1][0], out, blockbase + cp * P4, t0, lane);
    }
}

// ==================== fallback: R7-style (50.2us known-good) ====================
#define FB_P       4
#define FB_THREADS (FB_P * NTAB)             // 64
#define FB_STAGE   (FB_P * POS_BYTES)        // 20480
#define FB_BLOCKS  (NPOS / FB_P)             // 8192

__global__ __launch_bounds__(FB_THREADS) void engram_fb_kernel(
    const int* __restrict__ ids,
    const int* __restrict__ seeds,
    Tables tp,
    float* __restrict__ out)
{
    __shared__ __align__(16) unsigned char stage[FB_STAGE];
    __shared__ __align__(8)  unsigned long long mbar[FB_P];

    const int tid = threadIdx.x;
    const uint32_t stage_a = smem_u32(stage);
    const uint32_t mbar_a0 = smem_u32(mbar);

    if (tid < FB_P) {
        asm volatile("mbarrier.init.shared.b64 [%0], 1;"
                     :: "r"(mbar_a0 + tid * 8) : "memory");
    }
    __syncthreads();

    const int p    = tid >> 4;
    const int tab  = tid & 15;
    const int head = tab & 7;
    const int pos  = blockIdx.x * FB_P + p;
    const int s    = pos & (SEQ - 1);
    const uint32_t my_mbar = mbar_a0 + p * 8;

    uint64_t pol_ef, pol_el;
    asm("createpolicy.fractional.L2::evict_first.b64 %0, 1.0;" : "=l"(pol_ef));
    asm("createpolicy.fractional.L2::evict_last.b64 %0, 1.0;"  : "=l"(pol_el));

    const unsigned long long id0 = (unsigned int)__ldg(ids + pos);
    const unsigned long long id1 =
        (s >= 1) ? (unsigned long long)(unsigned int)__ldg(ids + pos - 1) : 0ull;

    unsigned long long h;
    if (tab < 8) {
        h = (id1 * (unsigned long long)(unsigned int)__ldg(seeds + head))
          ^ (id0 * (unsigned long long)(unsigned int)__ldg(seeds + 8 + head));
    } else {
        const unsigned long long id2 =
            (s >= 2) ? (unsigned long long)(unsigned int)__ldg(ids + pos - 2) : 0ull;
        h = (id2 * (unsigned long long)(unsigned int)__ldg(seeds + head))
          ^ (id1 * (unsigned long long)(unsigned int)__ldg(seeds + 8 + head))
          ^ (id0 * (unsigned long long)(unsigned int)__ldg(seeds + 16 + head));
    }
    const unsigned int idx = (unsigned int)(h % (unsigned long long)c_sizes[tab]);

    if (tab == 0) {
        asm volatile("mbarrier.arrive.expect_tx.shared.b64 _, [%0], %1;"
                     :: "r"(my_mbar), "r"((int)POS_BYTES) : "memory");
    }
    {
        const char*    src = (const char*)tp.t[tab] + (size_t)idx * ROW_BYTES;
        const uint32_t dst = stage_a + (uint32_t)tid * ROW_BYTES;
        asm volatile(
            "cp.async.bulk.shared::cta.global.mbarrier::complete_tx::bytes.L2::cache_hint "
            "[%0], [%1], %2, [%3], %4;"
            :: "r"(dst), "l"(src), "r"((int)ROW_BYTES), "r"(my_mbar), "l"(pol_el)
            : "memory");
    }

    if (tab == 0) {
        asm volatile(
            "{\n\t"
            ".reg .pred P1;\n\t"
            "W_%=:\n\t"
            "mbarrier.try_wait.parity.shared.b64 P1, [%0], 0, 0x989680;\n\t"
            "@P1 bra.uni D_%=;\n\t"
            "bra.uni W_%=;\n\t"
            "D_%=:\n\t"
            "}"
            :: "r"(my_mbar) : "memory");

        char* gdst = (char*)out + (size_t)pos * POS_BYTES;
        asm volatile(
            "cp.async.bulk.global.shared::cta.bulk_group.L2::cache_hint "
            "[%0], [%1], %2, %3;"
            :: "l"(gdst), "r"(stage_a + (uint32_t)p * POS_BYTES), "r"((int)POS_BYTES),
               "l"(pol_ef)
            : "memory");
        asm volatile("cp.async.bulk.commit_group;" ::: "memory");
        asm volatile("cp.async.bulk.wait_group.read 0;" ::: "memory");
    }
}

// ==================== host ====================
typedef CUresult (*PFN_encodeTiled)(
    CUtensorMap*, CUtensorMapDataType, cuuint32_t, void*,
    const cuuint64_t*, const cuuint64_t*, const cuuint32_t*, const cuuint32_t*,
    CUtensorMapInterleave, CUtensorMapSwizzle, CUtensorMapL2promotion,
    CUtensorMapFloatOOBfill);

extern "C" void kernel_launch(void* const* d_in, const int* in_sizes, int n_in,
                              void* d_out, int out_size)
{
    const int* ids   = (const int*)d_in[0];
    const int* seeds = (const int*)d_in[1];

    bool ok = false;
    TMaps maps;
    void* fp = nullptr;
    cudaDriverEntryPointQueryResult qres;
    if (cudaGetDriverEntryPointByVersion("cuTensorMapEncodeTiled", &fp, 12000,
                                         cudaEnableDefault, &qres) == cudaSuccess
        && fp != nullptr) {
        PFN_encodeTiled enc = (PFN_encodeTiled)fp;
        ok = true;
        for (int t = 0; t < 16 && ok; t++) {
            cuuint64_t dims[2]    = {(cuuint64_t)SLOT, (cuuint64_t)h_sizes[t]};
            cuuint64_t strides[1] = {(cuuint64_t)ROW_BYTES};
            cuuint32_t box[2]     = {(cuuint32_t)SLOT, 1u};
            cuuint32_t estr[2]    = {1u, 1u};
            CUresult r = enc(&maps.m[t], CU_TENSOR_MAP_DATA_TYPE_FLOAT32, 2,
                             (void*)d_in[2 + t], dims, strides, box, estr,
                             CU_TENSOR_MAP_INTERLEAVE_NONE,
                             CU_TENSOR_MAP_SWIZZLE_NONE,
                             CU_TENSOR_MAP_L2_PROMOTION_L2_128B,
                             CU_TENSOR_MAP_FLOAT_OOB_FILL_NONE);
            if (r != CUDA_SUCCESS) ok = false;
        }
    }

    if (ok) {
        engram_g4_kernel<<<G4_BLOCKS, G4_THREADS>>>(ids, seeds, maps, (float*)d_out);
    } else {
        Tables tp;
        for (int i = 0; i < 16; i++) tp.t[i] = (const float*)d_in[2 + i];
        engram_fb_kernel<<<FB_BLOCKS, FB_THREADS>>>(ids, seeds, tp, (float*)d_out);
    }
}

// round 16
// speedup vs baseline: 1.2858x; 1.0007x over previous
#include <cuda_runtime.h>
#include <cuda.h>
#include <stdint.h>

#define SEQ   4096
#define NPOS  32768
#define SLOT  80
#define ROW_BYTES (SLOT * 4)                 // 320
#define NTAB  16
#define POS_BYTES (NTAB * ROW_BYTES)         // 5120
#define P4    4                              // positions per block
#define TAB_STRIDE (P4 * ROW_BYTES)          // 1280 per gather4 result
#define STAGE_BYTES (NTAB * TAB_STRIDE)      // 20480 ([tab][p] layout)
#define G4_BLOCKS (NPOS / P4)                // 8192
#define G4_THREADS 128
#define WARP_BYTES (4 * TAB_STRIDE)          // 5120 per warp (4 tables)

__constant__ unsigned int c_sizes[16] = {
    6619u, 6637u, 6653u, 6659u, 6661u, 6673u, 6679u, 6689u,
    65521u, 65537u, 65539u, 65543u, 65551u, 65557u, 65563u, 65579u
};

static const unsigned int h_sizes[16] = {
    6619u, 6637u, 6653u, 6659u, 6661u, 6673u, 6679u, 6689u,
    65521u, 65537u, 65539u, 65543u, 65551u, 65557u, 65563u, 65579u
};

struct Tables { const float* t[16]; };
struct TMaps  { CUtensorMap m[17]; };        // 16 tables + 1 output (3D)

__device__ __forceinline__ uint32_t smem_u32(const void* p) {
    uint32_t a;
    asm("{ .reg .u64 tmp; cvta.to.shared.u64 tmp, %1; cvt.u32.u64 %0, tmp; }"
        : "=r"(a) : "l"(p));
    return a;
}

// ====== gather4 in, tensor-3d store out — warps fully independent, zero STG ======
__global__ __launch_bounds__(G4_THREADS) void engram_g4_kernel(
    const int* __restrict__ ids,
    const int* __restrict__ seeds,
    const __grid_constant__ TMaps maps)
{
    __shared__ __align__(128) unsigned char stage[STAGE_BYTES];  // [tab][p][320B]
    __shared__ __align__(8)  unsigned long long mbar[4];         // one per warp

    const int tid  = threadIdx.x;
    const int w    = tid >> 5;
    const int lane = tid & 31;
    const uint32_t stage_a = smem_u32(stage);
    const uint32_t my_mbar = smem_u32(&mbar[w]);

    if (lane == 0) {
        asm volatile("mbarrier.init.shared.b64 [%0], 1;" :: "r"(my_mbar) : "memory");
        asm volatile("mbarrier.arrive.expect_tx.shared.b64 _, [%0], %1;"
                     :: "r"(my_mbar), "r"((int)WARP_BYTES) : "memory");
    }
    __syncwarp();

    const int base = blockIdx.x * P4;
    const int t0   = w * 4;                   // this warp's first table

    uint64_t pol_ef, pol_el;
    asm("createpolicy.fractional.L2::evict_first.b64 %0, 1.0;" : "=l"(pol_ef));
    asm("createpolicy.fractional.L2::evict_last.b64 %0, 1.0;"  : "=l"(pol_el));

    // lanes 0-15: lane l -> table t0 + (l>>2), position l&3
    unsigned int idx = 0;
    if (lane < 16) {
        const int tab  = t0 + (lane >> 2);
        const int p    = lane & 3;
        const int head = tab & 7;
        const int pos  = base + p;
        const int s    = pos & (SEQ - 1);

        const unsigned long long id0 = (unsigned int)__ldg(ids + pos);
        const unsigned long long id1 =
            (s >= 1) ? (unsigned long long)(unsigned int)__ldg(ids + pos - 1) : 0ull;

        unsigned long long h;
        if (tab < 8) {
            h = (id1 * (unsigned long long)(unsigned int)__ldg(seeds + head))
              ^ (id0 * (unsigned long long)(unsigned int)__ldg(seeds + 8 + head));
        } else {
            const unsigned long long id2 =
                (s >= 2) ? (unsigned long long)(unsigned int)__ldg(ids + pos - 2) : 0ull;
            h = (id2 * (unsigned long long)(unsigned int)__ldg(seeds + head))
              ^ (id1 * (unsigned long long)(unsigned int)__ldg(seeds + 8 + head))
              ^ (id0 * (unsigned long long)(unsigned int)__ldg(seeds + 16 + head));
        }
        idx = (unsigned int)(h % (unsigned long long)c_sizes[tab]);
    }

    // collect 4 position-indices into the group leaders (lanes 0,4,8,12)
    const unsigned y0 = __shfl_sync(0xFFFFFFFFu, idx, (lane & 12) | 0);
    const unsigned y1 = __shfl_sync(0xFFFFFFFFu, idx, (lane & 12) | 1);
    const unsigned y2 = __shfl_sync(0xFFFFFFFFu, idx, (lane & 12) | 2);
    const unsigned y3 = __shfl_sync(0xFFFFFFFFu, idx, (lane & 12) | 3);

    const int  tl  = lane >> 2;               // table-local 0..3 (for leaders)
    const int  tab = t0 + tl;
    const uint32_t tdst = stage_a + (uint32_t)tab * TAB_STRIDE;

    if (lane < 16 && (lane & 3) == 0) {
        asm volatile(
            "cp.async.bulk.tensor.2d.shared::cta.global.tile::gather4"
            ".mbarrier::complete_tx::bytes.L2::cache_hint "
            "[%0], [%1, {%2, %3, %4, %5, %6}], [%7], %8;"
            :: "r"(tdst), "l"(&maps.m[tab]),
               "r"(0), "r"((int)y0), "r"((int)y1), "r"((int)y2), "r"((int)y3),
               "r"(my_mbar), "l"(pol_el)
            : "memory");
    }

    // warp-local wait (acquire) for its own 5120B
    asm volatile(
        "{\n\t"
        ".reg .pred P1;\n\t"
        "W_%=:\n\t"
        "mbarrier.try_wait.parity.acquire.cta.shared::cta.b64 P1, [%0], 0, 0x989680;\n\t"
        "@P1 bra.uni D_%=;\n\t"
        "bra.uni W_%=;\n\t"
        "D_%=:\n\t"
        "}"
        :: "r"(my_mbar) : "memory");

    // drain via TMA 3D store: box (80,1,4) = this table's 4 rows (1280B smem)
    // -> global [pos..pos+3][tab][0..80)
    if (lane < 16 && (lane & 3) == 0) {
        asm volatile(
            "cp.async.bulk.tensor.3d.global.shared::cta.tile.bulk_group"
            ".L2::cache_hint "
            "[%0, {%1, %2, %3}], [%4], %5;"
            :: "l"(&maps.m[16]), "r"(0), "r"(tab), "r"(base),
               "r"(tdst), "l"(pol_ef)
            : "memory");
        asm volatile("cp.async.bulk.commit_group;" ::: "memory");
        asm volatile("cp.async.bulk.wait_group.read 0;" ::: "memory");
    }
}

// ==================== fallback: R14 (47.9us known-good, STG drain) ====================
__global__ __launch_bounds__(G4_THREADS) void engram_g4stg_kernel(
    const int* __restrict__ ids,
    const int* __restrict__ seeds,
    const __grid_constant__ TMaps maps,
    float* __restrict__ out)
{
    __shared__ __align__(128) unsigned char stage[STAGE_BYTES];
    __shared__ __align__(8)  unsigned long long mbar[4];

    const int tid  = threadIdx.x;
    const int w    = tid >> 5;
    const int lane = tid & 31;
    const uint32_t stage_a = smem_u32(stage);
    const uint32_t my_mbar = smem_u32(&mbar[w]);

    if (lane == 0) {
        asm volatile("mbarrier.init.shared.b64 [%0], 1;" :: "r"(my_mbar) : "memory");
        asm volatile("mbarrier.arrive.expect_tx.shared.b64 _, [%0], %1;"
                     :: "r"(my_mbar), "r"((int)WARP_BYTES) : "memory");
    }
    __syncwarp();

    const int base = blockIdx.x * P4;
    const int t0   = w * 4;

    uint64_t pol_el;
    asm("createpolicy.fractional.L2::evict_last.b64 %0, 1.0;" : "=l"(pol_el));

    unsigned int idx = 0;
    if (lane < 16) {
        const int tab  = t0 + (lane >> 2);
        const int p    = lane & 3;
        const int head = tab & 7;
        const int pos  = base + p;
        const int s    = pos & (SEQ - 1);

        const unsigned long long id0 = (unsigned int)__ldg(ids + pos);
        const unsigned long long id1 =
            (s >= 1) ? (unsigned long long)(unsigned int)__ldg(ids + pos - 1) : 0ull;

        unsigned long long h;
        if (tab < 8) {
            h = (id1 * (unsigned long long)(unsigned int)__ldg(seeds + head))
              ^ (id0 * (unsigned long long)(unsigned int)__ldg(seeds + 8 + head));
        } else {
            const unsigned long long id2 =
                (s >= 2) ? (unsigned long long)(unsigned int)__ldg(ids + pos - 2) : 0ull;
            h = (id2 * (unsigned long long)(unsigned int)__ldg(seeds + head))
              ^ (id1 * (unsigned long long)(unsigned int)__ldg(seeds + 8 + head))
              ^ (id0 * (unsigned long long)(unsigned int)__ldg(seeds + 16 + head));
        }
        idx = (unsigned int)(h % (unsigned long long)c_sizes[tab]);
    }

    const unsigned y0 = __shfl_sync(0xFFFFFFFFu, idx, (lane & 12) | 0);
    const unsigned y1 = __shfl_sync(0xFFFFFFFFu, idx, (lane & 12) | 1);
    const unsigned y2 = __shfl_sync(0xFFFFFFFFu, idx, (lane & 12) | 2);
    const unsigned y3 = __shfl_sync(0xFFFFFFFFu, idx, (lane & 12) | 3);

    if (lane < 16 && (lane & 3) == 0) {
        const int tab = t0 + (lane >> 2);
        const uint32_t dst = stage_a + (uint32_t)tab * TAB_STRIDE;
        asm volatile(
            "cp.async.bulk.tensor.2d.shared::cta.global.tile::gather4"
            ".mbarrier::complete_tx::bytes.L2::cache_hint "
            "[%0], [%1, {%2, %3, %4, %5, %6}], [%7], %8;"
            :: "r"(dst), "l"(&maps.m[tab]),
               "r"(0), "r"((int)y0), "r"((int)y1), "r"((int)y2), "r"((int)y3),
               "r"(my_mbar), "l"(pol_el)
            : "memory");
    }

    asm volatile(
        "{\n\t"
        ".reg .pred P1;\n\t"
        "W_%=:\n\t"
        "mbarrier.try_wait.parity.acquire.cta.shared::cta.b64 P1, [%0], 0, 0x989680;\n\t"
        "@P1 bra.uni D_%=;\n\t"
        "bra.uni W_%=;\n\t"
        "D_%=:\n\t"
        "}"
        :: "r"(my_mbar) : "memory");

    const unsigned char* wsrc = stage + (size_t)t0 * TAB_STRIDE;
    float* gbase = out + (size_t)base * (POS_BYTES / 4) + (size_t)t0 * SLOT;
    #pragma unroll
    for (int i = 0; i < 10; i++) {
        const int f   = i * 32 + lane;
        const int tt  = f / 80;
        const int rem = f - tt * 80;
        const int p   = rem / 20;
        const int q   = rem - p * 20;
        const float4 v = *(const float4*)(wsrc + (tt * P4 + p) * ROW_BYTES + q * 16);
        __stcs((float4*)(gbase + (size_t)p * (POS_BYTES / 4) + tt * SLOT + q * 4), v);
    }
}

// ==================== fallback 2: R7-style (no tensor maps at all) ====================
#define FB_P       4
#define FB_THREADS (FB_P * NTAB)
#define FB_STAGE   (FB_P * POS_BYTES)
#define FB_BLOCKS  (NPOS / FB_P)

__global__ __launch_bounds__(FB_THREADS) void engram_fb_kernel(
    const int* __restrict__ ids,
    const int* __restrict__ seeds,
    Tables tp,
    float* __restrict__ out)
{
    __shared__ __align__(16) unsigned char stage[FB_STAGE];
    __shared__ __align__(8)  unsigned long long mbar[FB_P];

    const int tid = threadIdx.x;
    const uint32_t stage_a = smem_u32(stage);
    const uint32_t mbar_a0 = smem_u32(mbar);

    if (tid < FB_P) {
        asm volatile("mbarrier.init.shared.b64 [%0], 1;"
                     :: "r"(mbar_a0 + tid * 8) : "memory");
    }
    __syncthreads();

    const int p    = tid >> 4;
    const int tab  = tid & 15;
    const int head = tab & 7;
    const int pos  = blockIdx.x * FB_P + p;
    const int s    = pos & (SEQ - 1);
    const uint32_t my_mbar = mbar_a0 + p * 8;

    uint64_t pol_ef, pol_el;
    asm("createpolicy.fractional.L2::evict_first.b64 %0, 1.0;" : "=l"(pol_ef));
    asm("createpolicy.fractional.L2::evict_last.b64 %0, 1.0;"  : "=l"(pol_el));

    const unsigned long long id0 = (unsigned int)__ldg(ids + pos);
    const unsigned long long id1 =
        (s >= 1) ? (unsigned long long)(unsigned int)__ldg(ids + pos - 1) : 0ull;

    unsigned long long h;
    if (tab < 8) {
        h = (id1 * (unsigned long long)(unsigned int)__ldg(seeds + head))
          ^ (id0 * (unsigned long long)(unsigned int)__ldg(seeds + 8 + head));
    } else {
        const unsigned long long id2 =
            (s >= 2) ? (unsigned long long)(unsigned int)__ldg(ids + pos - 2) : 0ull;
        h = (id2 * (unsigned long long)(unsigned int)__ldg(seeds + head))
          ^ (id1 * (unsigned long long)(unsigned int)__ldg(seeds + 8 + head))
          ^ (id0 * (unsigned long long)(unsigned int)__ldg(seeds + 16 + head));
    }
    const unsigned int idx = (unsigned int)(h % (unsigned long long)c_sizes[tab]);

    if (tab == 0) {
        asm volatile("mbarrier.arrive.expect_tx.shared.b64 _, [%0], %1;"
                     :: "r"(my_mbar), "r"((int)POS_BYTES) : "memory");
    }
    {
        const char*    src = (const char*)tp.t[tab] + (size_t)idx * ROW_BYTES;
        const uint32_t dst = stage_a + (uint32_t)tid * ROW_BYTES;
        asm volatile(
            "cp.async.bulk.shared::cta.global.mbarrier::complete_tx::bytes.L2::cache_hint "
            "[%0], [%1], %2, [%3], %4;"
            :: "r"(dst), "l"(src), "r"((int)ROW_BYTES), "r"(my_mbar), "l"(pol_el)
            : "memory");
    }

    if (tab == 0) {
        asm volatile(
            "{\n\t"
            ".reg .pred P1;\n\t"
            "W_%=:\n\t"
            "mbarrier.try_wait.parity.shared.b64 P1, [%0], 0, 0x989680;\n\t"
            "@P1 bra.uni D_%=;\n\t"
            "bra.uni W_%=;\n\t"
            "D_%=:\n\t"
            "}"
            :: "r"(my_mbar) : "memory");

        char* gdst = (char*)out + (size_t)pos * POS_BYTES;
        asm volatile(
            "cp.async.bulk.global.shared::cta.bulk_group.L2::cache_hint "
            "[%0], [%1], %2, %3;"
            :: "l"(gdst), "r"(stage_a + (uint32_t)p * POS_BYTES), "r"((int)POS_BYTES),
               "l"(pol_ef)
            : "memory");
        asm volatile("cp.async.bulk.commit_group;" ::: "memory");
        asm volatile("cp.async.bulk.wait_group.read 0;" ::: "memory");
    }
}

// ==================== host ====================
typedef CUresult (*PFN_encodeTiled)(
    CUtensorMap*, CUtensorMapDataType, cuuint32_t, void*,
    const cuuint64_t*, const cuuint64_t*, const cuuint32_t*, const cuuint32_t*,
    CUtensorMapInterleave, CUtensorMapSwizzle, CUtensorMapL2promotion,
    CUtensorMapFloatOOBfill);

extern "C" void kernel_launch(void* const* d_in, const int* in_sizes, int n_in,
                              void* d_out, int out_size)
{
    const int* ids   = (const int*)d_in[0];
    const int* seeds = (const int*)d_in[1];

    bool ok = false;       // 16 table maps encoded
    bool ok_out = false;   // output 3D map encoded
    TMaps maps;
    void* fp = nullptr;
    cudaDriverEntryPointQueryResult qres;
    if (cudaGetDriverEntryPointByVersion("cuTensorMapEncodeTiled", &fp, 12000,
                                         cudaEnableDefault, &qres) == cudaSuccess
        && fp != nullptr) {
        PFN_encodeTiled enc = (PFN_encodeTiled)fp;
        ok = true;
        for (int t = 0; t < 16 && ok; t++) {
            cuuint64_t dims[2]    = {(cuuint64_t)SLOT, (cuuint64_t)h_sizes[t]};
            cuuint64_t strides[1] = {(cuuint64_t)ROW_BYTES};
            cuuint32_t box[2]     = {(cuuint32_t)SLOT, 1u};
            cuuint32_t estr[2]    = {1u, 1u};
            CUresult r = enc(&maps.m[t], CU_TENSOR_MAP_DATA_TYPE_FLOAT32, 2,
                             (void*)d_in[2 + t], dims, strides, box, estr,
                             CU_TENSOR_MAP_INTERLEAVE_NONE,
                             CU_TENSOR_MAP_SWIZZLE_NONE,
                             CU_TENSOR_MAP_L2_PROMOTION_L2_128B,
                             CU_TENSOR_MAP_FLOAT_OOB_FILL_NONE);
            if (r != CUDA_SUCCESS) ok = false;
        }
        if (ok) {
            // output as 3D tensor [pos][tab][80 floats]
            cuuint64_t dims[3]    = {(cuuint64_t)SLOT, (cuuint64_t)NTAB, (cuuint64_t)NPOS};
            cuuint64_t strides[2] = {(cuuint64_t)ROW_BYTES, (cuuint64_t)POS_BYTES};
            cuuint32_t box[3]     = {(cuuint32_t)SLOT, 1u, (cuuint32_t)P4};
            cuuint32_t estr[3]    = {1u, 1u, 1u};
            CUresult r = enc(&maps.m[16], CU_TENSOR_MAP_DATA_TYPE_FLOAT32, 3,
                             d_out, dims, strides, box, estr,
                             CU_TENSOR_MAP_INTERLEAVE_NONE,
                             CU_TENSOR_MAP_SWIZZLE_NONE,
                             CU_TENSOR_MAP_L2_PROMOTION_L2_128B,
                             CU_TENSOR_MAP_FLOAT_OOB_FILL_NONE);
            ok_out = (r == CUDA_SUCCESS);
        }
    }

    if (ok && ok_out) {
        engram_g4_kernel<<<G4_BLOCKS, G4_THREADS>>>(ids, seeds, maps);
    } else if (ok) {
        engram_g4stg_kernel<<<G4_BLOCKS, G4_THREADS>>>(ids, seeds, maps, (float*)d_out);
    } else {
        Tables tp;
        for (int i = 0; i < 16; i++) tp.t[i] = (const float*)d_in[2 + i];
        engram_fb_kernel<<<FB_BLOCKS, FB_THREADS>>>(ids, seeds, tp, (float*)d_out);
    }
}